// round 16
// baseline (speedup 1.0000x reference)
#include <cuda_runtime.h>
#include <cuda_fp16.h>
#include <cstdint>

#define DIM 256
#define NMOD 5
#define NROWS 16384
#define TB 64
#define NTH 512
#define XPITCH (NMOD * DIM)

#define APITCH 264            // A_s pitch (fp16)
#define BPITCH 72             // B pitch (fp16), 64 K-cols + 8 pad
#define SPITCH 264            // stage pitch (fp16)
#define CHUNK_BYTES (256 * BPITCH * 2)   // 36864
#define CHUNK_U16   (CHUNK_BYTES / 16)   // 2304

// Fused per-branch matrices, PRE-PADDED fp16 image (chunk c = n*4+kc).
__device__ __align__(16) __half g_M[NMOD * 4][256][BPITCH];
__device__ float g_c[NMOD][DIM];

// ---------------- main-kernel smem layout ----------------
constexpr int SM_GA  = 0;                        // gates 64*8 f     = 2048
constexpr int SM_STG = 2048;                     // 64*264 fp16      = 33792
constexpr int SM_A   = SM_STG + 33792;           // 2 x 64*264 fp16  = 67584
constexpr int SM_B   = SM_A + 67584;             // 2 x 36864        = 73728
constexpr int SMEM_TOTAL = SM_B + 73728;         // 177152

// named barriers
#define BID_AREADY 1
#define BID_SFULL  2
#define BID_SFREE  3
#define BID_PROD   6
#define BAR_SYNC(id, cnt)   asm volatile("bar.sync %0, %1;"   :: "r"(id), "r"(cnt) : "memory")
#define BAR_ARRIVE(id, cnt) asm volatile("bar.arrive %0, %1;" :: "r"(id), "r"(cnt) : "memory")

// ---------------- helpers ----------------
__device__ __forceinline__ void ldsm_x4(uint32_t* r, const void* p) {
    uint32_t addr = (uint32_t)__cvta_generic_to_shared(p);
    asm volatile("ldmatrix.sync.aligned.m8n8.x4.shared.b16 {%0,%1,%2,%3}, [%4];"
                 : "=r"(r[0]), "=r"(r[1]), "=r"(r[2]), "=r"(r[3]) : "r"(addr));
}
__device__ __forceinline__ void mma16816f(float* d, const uint32_t* a, const uint32_t* b) {
    asm volatile("mma.sync.aligned.m16n8k16.row.col.f32.f16.f16.f32 "
                 "{%0,%1,%2,%3},{%4,%5,%6,%7},{%8,%9},{%0,%1,%2,%3};"
                 : "+f"(d[0]), "+f"(d[1]), "+f"(d[2]), "+f"(d[3])
                 : "r"(a[0]), "r"(a[1]), "r"(a[2]), "r"(a[3]), "r"(b[0]), "r"(b[1]));
}
__device__ __forceinline__ float warp_sum(float v) {
#pragma unroll
    for (int o = 16; o; o >>= 1) v += __shfl_xor_sync(0xffffffffu, v, o);
    return v;
}
__device__ __forceinline__ void cp_async16(void* smem, const void* g) {
    uint32_t s = (uint32_t)__cvta_generic_to_shared(smem);
    asm volatile("cp.async.cg.shared.global [%0], [%1], 16;\n" :: "r"(s), "l"(g));
}
__device__ __forceinline__ void cp_commit() { asm volatile("cp.async.commit_group;\n"); }
__device__ __forceinline__ uint32_t pkh2(float a, float b) {
    __half2 h = __floats2half2_rn(a, b);
    return *(uint32_t*)&h;
}

// ------------------------------------------------------------------
// prologue v2: grid (8, 4, 5) = 160 CTAs. CTA (bx, kc, n) computes the
// 32x64 output tile M_n[bx*32..+32][kc*64..+64] with K=256 resident.
// Single sync phase. Bias computed by kc==0 CTAs.
// smem: A_s [32][264] fp16 (16896) | B_s [64][264] fp16 (33792) | bv 1024
// ------------------------------------------------------------------
constexpr int PSM_TOTAL = 16896 + 33792 + 1024;   // 51712

__global__ __launch_bounds__(256, 1)
void fuse_weights_kernel(const float* __restrict__ sWi, const float* __restrict__ sbi,
                         const float* __restrict__ sWo, const float* __restrict__ sbo,
                         const float* __restrict__ cWi, const float* __restrict__ cbi,
                         const float* __restrict__ cWo, const float* __restrict__ cbo) {
    extern __shared__ char sm[];
    __half* A_s = (__half*)sm;                       // [32][APITCH]
    __half* B_s = (__half*)(sm + 16896);             // [64][APITCH]  (k rows, j cols)
    float* bv_s = (float*)(sm + 16896 + 33792);      // [256]
    float* bred = (float*)B_s;                       // reuse after GEMM

    const int bx = blockIdx.x, kc = blockIdx.y, n = blockIdx.z;
    const float* Wo = (n == 0) ? sWo : cWo + (size_t)(n - 1) * DIM * DIM;
    const float* Wv = (n == 0) ? sWi + 2 * DIM * DIM
                               : cWi + (size_t)(n - 1) * 3 * DIM * DIM + 2 * DIM * DIM;
    const float* bv = (n == 0) ? sbi + 2 * DIM : cbi + (size_t)(n - 1) * 3 * DIM + 2 * DIM;
    const float* bo = (n == 0) ? sbo : cbo + (size_t)(n - 1) * DIM;

    const int tid = threadIdx.x;
    const int w = tid >> 5, l = tid & 31;
    const int wm = w & 1, wn = w >> 1;
    const int lq = l >> 2, lr = l & 3;

    bv_s[tid] = bv[tid];

    // A: Wo rows bx*32..+31, all 256 j  (fp16)
#pragma unroll
    for (int i = 0; i < 8; i++) {
        int e = tid + i * 256, r = e >> 6, c4 = (e & 63) << 2;
        float4 v = *(const float4*)(Wo + (size_t)(bx * 32 + r) * DIM + c4);
        __half* dst = A_s + r * APITCH + c4;
        *(uint32_t*)(dst)     = pkh2(v.x, v.y);
        *(uint32_t*)(dst + 2) = pkh2(v.z, v.w);
    }
    // B: B_s[k][j] = Wv[j][kc*64 + k], k 0..63, j 0..255 (coalesced along k)
#pragma unroll
    for (int i = 0; i < 16; i++) {
        int e = tid + i * 256;
        int k = e & 63, j4 = (e >> 6) << 2;
        float v0 = Wv[(size_t)(j4 + 0) * DIM + kc * 64 + k];
        float v1 = Wv[(size_t)(j4 + 1) * DIM + kc * 64 + k];
        float v2 = Wv[(size_t)(j4 + 2) * DIM + kc * 64 + k];
        float v3 = Wv[(size_t)(j4 + 3) * DIM + kc * 64 + k];
        __half* dst = B_s + k * APITCH + j4;
        *(uint32_t*)(dst)     = pkh2(v0, v1);
        *(uint32_t*)(dst + 2) = pkh2(v2, v3);
    }
    __syncthreads();

    // warp tile 16x16 (2M x 4N), K=256 in 16 ks steps, no barriers
    float cf[2][4];
#pragma unroll
    for (int nt = 0; nt < 2; nt++)
#pragma unroll
        for (int i = 0; i < 4; i++) cf[nt][i] = 0.f;

#pragma unroll
    for (int ks = 0; ks < 16; ks++) {
        uint32_t af[4];
        {
            int row = wm * 16 + (l & 7) + ((l >> 3) & 1) * 8;
            int col = ks * 16 + (l >> 4) * 8;
            ldsm_x4(af, A_s + row * APITCH + col);
        }
        uint32_t r4[4];
        {
            int row = wn * 16 + (l & 7) + (l >> 4) * 8;
            int col = ks * 16 + ((l >> 3) & 1) * 8;
            ldsm_x4(r4, B_s + row * APITCH + col);
        }
        mma16816f(cf[0], af, r4);
        mma16816f(cf[1], af, r4 + 2);
    }
    __syncthreads();   // B_s reads done (bred reuses it in kc==0)

    // store 32x64 tile to padded image chunk ch = n*4+kc
    {
        int ch = n * 4 + kc;
        int d = bx * 32 + wm * 16 + lq;
#pragma unroll
        for (int nt = 0; nt < 2; nt++) {
            int kk = wn * 16 + nt * 8 + 2 * lr;
            *(uint32_t*)&g_M[ch][d][kk]     = pkh2(cf[nt][0], cf[nt][1]);
            *(uint32_t*)&g_M[ch][d + 8][kk] = pkh2(cf[nt][2], cf[nt][3]);
        }
    }

    // bias (kc==0 CTAs only): c[d] = Wo[d,:] @ bv + bo[d]
    if (kc == 0) {
        int row = tid & 31, part = tid >> 5;
        float s = 0.f;
#pragma unroll 8
        for (int j = 0; j < 32; j++) {
            int jj = part * 32 + j;
            s += __half2float(A_s[row * APITCH + jj]) * bv_s[jj];
        }
        bred[part * 32 + row] = s;
        __syncthreads();
        if (tid < 32) {
            float c = bo[bx * 32 + tid];
#pragma unroll
            for (int p = 0; p < 8; p++) c += bred[p * 32 + tid];
            g_c[n][bx * 32 + tid] = c;
        }
    }
}

// ------------------------------------------------------------------
// main kernel: warp-specialized producer/consumer (R13/R15 structure),
// gates now 2-row interleaved like the cross-LN path.
// ------------------------------------------------------------------
__global__ __launch_bounds__(NTH, 1)
void fused_main_kernel(const float* __restrict__ x,
                       const float* __restrict__ cross_ln_g, const float* __restrict__ cross_ln_b,
                       const float* __restrict__ gate_ln_g, const float* __restrict__ gate_ln_b,
                       const float* __restrict__ gate_W, const float* __restrict__ gate_b,
                       const float* __restrict__ final_ln_g, const float* __restrict__ final_ln_b,
                       const int* __restrict__ modal_idx, float* __restrict__ out) {
    extern __shared__ char sm[];
    float* gates_s = (float*)(sm + SM_GA);      // [64][8]
    __half* stg    = (__half*)(sm + SM_STG);    // [64][SPITCH] fp16
    __half* A_s    = (__half*)(sm + SM_A);      // [2][64][APITCH]
    char* B_s      = sm + SM_B;                 // [2][CHUNK_BYTES]

    const int tid = threadIdx.x;
    const int w = tid >> 5, l = tid & 31;
    const int mi = *modal_idx;
    const int r0 = blockIdx.x * TB;

    // producers issue B prefetch (chunks 0,1)
    if (tid < 256) {
        const char* src = (const char*)g_M;
#pragma unroll
        for (int i = 0; i < 9; i++) {
            int e = tid + i * 256;
            if (e < CHUNK_U16) cp_async16(B_s + e * 16, src + e * 16);
        }
        cp_commit();
#pragma unroll
        for (int i = 0; i < 9; i++) {
            int e = tid + i * 256;
            if (e < CHUNK_U16) cp_async16(B_s + CHUNK_BYTES + e * 16, src + CHUNK_BYTES + e * 16);
        }
        cp_commit();
    }

    // A0 fill by all 512 threads (branch 0 = modality mi)
#pragma unroll
    for (int i = 0; i < 8; i++) {
        int e = tid + i * NTH, r = e >> 6, c4 = (e & 63) << 2;
        float4 v = *(const float4*)(x + (size_t)(r0 + r) * XPITCH + mi * DIM + c4);
        __half* dst = A_s + r * APITCH + c4;
        *(uint32_t*)(dst)     = pkh2(v.x, v.y);
        *(uint32_t*)(dst + 2) = pkh2(v.z, v.w);
    }
    __syncthreads();

    if (w < 8) {
        // ===================== PRODUCER (8 warps) =====================
        const int wm = w & 1, wn = w >> 1;
        const int lq = l >> 2, lr = l & 3;

#pragma unroll 1
        for (int n = 0; n < NMOD; n++) {
            if (n) BAR_SYNC(BID_AREADY, 512);     // A[n&1] filled by consumers
            const __half* As = A_s + (n & 1) * (TB * APITCH);

            float cf[2][8][4];
#pragma unroll
            for (int mt = 0; mt < 2; mt++)
#pragma unroll
                for (int nt = 0; nt < 8; nt++)
#pragma unroll
                    for (int i = 0; i < 4; i++) cf[mt][nt][i] = 0.f;

#pragma unroll 1
            for (int kc = 0; kc < 4; kc++) {
                int c = n * 4 + kc;
                asm volatile("cp.async.wait_group 0;\n");
                BAR_SYNC(BID_PROD, 256);          // chunk c visible; old buf free
                if (c + 1 < 20) {
                    const char* src = (const char*)g_M + (size_t)(c + 1) * CHUNK_BYTES;
                    char* dst = B_s + ((c + 1) & 1) * CHUNK_BYTES;
#pragma unroll
                    for (int i = 0; i < 9; i++) {
                        int e = tid + i * 256;
                        if (e < CHUNK_U16) cp_async16(dst + e * 16, src + e * 16);
                    }
                    cp_commit();
                }
                const __half* Bc = (const __half*)(B_s + (c & 1) * CHUNK_BYTES);
#pragma unroll
                for (int ks = 0; ks < 4; ks++) {
                    uint32_t af[2][4];
#pragma unroll
                    for (int mt = 0; mt < 2; mt++) {
                        int row = wm * 32 + mt * 16 + (l & 7) + ((l >> 3) & 1) * 8;
                        int col = kc * 64 + ks * 16 + (l >> 4) * 8;
                        ldsm_x4(af[mt], As + row * APITCH + col);
                    }
                    uint32_t bfr[8][2];
#pragma unroll
                    for (int np = 0; np < 4; np++) {
                        int row = wn * 64 + np * 16 + (l & 7) + (l >> 4) * 8;
                        int col = ks * 16 + ((l >> 3) & 1) * 8;
                        uint32_t r4[4];
                        ldsm_x4(r4, Bc + row * BPITCH + col);
                        bfr[2 * np][0] = r4[0]; bfr[2 * np][1] = r4[1];
                        bfr[2 * np + 1][0] = r4[2]; bfr[2 * np + 1][1] = r4[3];
                    }
#pragma unroll
                    for (int mt = 0; mt < 2; mt++)
#pragma unroll
                        for (int nt = 0; nt < 8; nt++)
                            mma16816f(cf[mt][nt], af[mt], bfr[nt]);
                }
            }

            // publish a-tile to stage (fp16)
            if (n) BAR_SYNC(BID_SFREE, 512);      // consumers drained stage n-1
#pragma unroll
            for (int mt = 0; mt < 2; mt++)
#pragma unroll
                for (int nt = 0; nt < 8; nt++) {
                    int row = wm * 32 + mt * 16 + lq;
                    int col = wn * 64 + nt * 8 + 2 * lr;
                    *(uint32_t*)(stg + row * SPITCH + col)       = pkh2(cf[mt][nt][0], cf[mt][nt][1]);
                    *(uint32_t*)(stg + (row + 8) * SPITCH + col) = pkh2(cf[mt][nt][2], cf[mt][nt][3]);
                }
            __threadfence_block();
            BAR_ARRIVE(BID_SFULL, 512);
        }
    } else {
        // ===================== CONSUMER (8 warps) =====================
        const int cw = w - 8;            // 0..7, owns rows cw*8 .. cw*8+7
        const int ctid = tid - 256;      // 0..255

        // gates for my 8 rows, 2-row interleaved (overlaps producer GEMM 0)
        {
            float gb[5];
#pragma unroll
            for (int n = 0; n < 5; n++) gb[n] = __ldg(gate_b + n);
#pragma unroll 1
            for (int rp = 0; rp < 4; rp++) {
                int ra = cw * 8 + rp * 2, rb = ra + 1;
                const float* qra = x + (size_t)(r0 + ra) * XPITCH + mi * DIM;
                const float* qrb = x + (size_t)(r0 + rb) * XPITCH + mi * DIM;
                float qa[8], qb[8];
                float sa = 0.f, ssa = 0.f, sb = 0.f, ssb = 0.f;
#pragma unroll
                for (int j = 0; j < 8; j++) {
                    int c = l + 32 * j;
                    qa[j] = qra[c]; qb[j] = qrb[c];
                    sa += qa[j]; ssa += qa[j] * qa[j];
                    sb += qb[j]; ssb += qb[j] * qb[j];
                }
#pragma unroll
                for (int o = 16; o; o >>= 1) {
                    sa  += __shfl_xor_sync(0xffffffffu, sa, o);
                    ssa += __shfl_xor_sync(0xffffffffu, ssa, o);
                    sb  += __shfl_xor_sync(0xffffffffu, sb, o);
                    ssb += __shfl_xor_sync(0xffffffffu, ssb, o);
                }
                float ma = sa * (1.f / DIM);
                float rsa = rsqrtf(fmaxf(ssa * (1.f / DIM) - ma * ma, 0.f) + 1e-5f);
                float mb = sb * (1.f / DIM);
                float rsb = rsqrtf(fmaxf(ssb * (1.f / DIM) - mb * mb, 0.f) + 1e-5f);
                float lnva[8], lnvb[8];
#pragma unroll
                for (int j = 0; j < 8; j++) {
                    int c = l + 32 * j;
                    float gg = __ldg(gate_ln_g + c), bb = __ldg(gate_ln_b + c);
                    lnva[j] = (qa[j] - ma) * rsa * gg + bb;
                    lnvb[j] = (qb[j] - mb) * rsb * gg + bb;
                }
                float lga[5], lgb[5];
#pragma unroll
                for (int n = 0; n < 5; n++) {
                    float sA = 0.f, sB = 0.f;
#pragma unroll
                    for (int j = 0; j < 8; j++) {
                        float ww = __ldg(gate_W + n * DIM + l + 32 * j);
                        sA += lnva[j] * ww; sB += lnvb[j] * ww;
                    }
#pragma unroll
                    for (int o = 16; o; o >>= 1) {
                        sA += __shfl_xor_sync(0xffffffffu, sA, o);
                        sB += __shfl_xor_sync(0xffffffffu, sB, o);
                    }
                    lga[n] = sA + gb[n]; lgb[n] = sB + gb[n];
                }
                float mxa = lga[0], mxb = lgb[0];
#pragma unroll
                for (int n = 1; n < 5; n++) { mxa = fmaxf(mxa, lga[n]); mxb = fmaxf(mxb, lgb[n]); }
                float esa = 0.f, esb = 0.f;
#pragma unroll
                for (int n = 0; n < 5; n++) {
                    lga[n] = expf(lga[n] - mxa); esa += lga[n];
                    lgb[n] = expf(lgb[n] - mxb); esb += lgb[n];
                }
                if (l == 0) {
                    float inva = 1.f / esa, invb = 1.f / esb;
#pragma unroll
                    for (int n = 0; n < 5; n++) {
                        gates_s[ra * 8 + n] = lga[n] * inva;
                        gates_s[rb * 8 + n] = lgb[n] * invb;
                    }
                }
            }
            __syncwarp();
        }

        float acc[8][8];

#pragma unroll 1
        for (int n = 0; n < NMOD; n++) {
            // fill A for branch n+1 (buffer (n+1)&1 free: GEMM n-1 done)
            if (n + 1 < NMOD) {
                int m2 = n + 1;
                int mod = ((m2 - 1) < mi) ? (m2 - 1) : m2;
                __half* Ad = A_s + (m2 & 1) * (TB * APITCH);
#pragma unroll
                for (int i = 0; i < 16; i++) {
                    int e = ctid + i * 256, r = e >> 6, c4 = (e & 63) << 2;
                    float4 v = *(const float4*)(x + (size_t)(r0 + r) * XPITCH + mod * DIM + c4);
                    __half* dst = Ad + r * APITCH + c4;
                    *(uint32_t*)(dst)     = pkh2(v.x, v.y);
                    *(uint32_t*)(dst + 2) = pkh2(v.z, v.w);
                }
                __threadfence_block();
                BAR_ARRIVE(BID_AREADY, 512);
            }

            BAR_SYNC(BID_SFULL, 512);   // stage n ready

            if (n == 0) {
                float c0[8];
#pragma unroll
                for (int j = 0; j < 8; j++) c0[j] = g_c[0][l + 32 * j];
#pragma unroll
                for (int ri = 0; ri < 8; ri++) {
                    int row = cw * 8 + ri;
                    float g0 = gates_s[row * 8 + 0];
#pragma unroll
                    for (int j = 0; j < 8; j++)
                        acc[ri][j] = g0 * (__half2float(stg[row * SPITCH + l + 32 * j]) + c0[j]);
                }
            } else {
                float cn[8], gm[8], bt[8];
                const float* gam = cross_ln_g + (n - 1) * DIM;
                const float* bet = cross_ln_b + (n - 1) * DIM;
#pragma unroll
                for (int j = 0; j < 8; j++) {
                    int c = l + 32 * j;
                    cn[j] = g_c[n][c]; gm[j] = __ldg(gam + c); bt[j] = __ldg(bet + c);
                }
#pragma unroll
                for (int rp = 0; rp < 4; rp++) {
                    int ra = cw * 8 + rp * 2, rb = ra + 1;
                    const float* qa = x + (size_t)(r0 + ra) * XPITCH + mi * DIM;
                    const float* qb = x + (size_t)(r0 + rb) * XPITCH + mi * DIM;
                    float ta[8], tb2[8];
                    float sa = 0.f, ssa = 0.f, sb = 0.f, ssb = 0.f;
#pragma unroll
                    for (int j = 0; j < 8; j++) {
                        int c = l + 32 * j;
                        ta[j]  = qa[c] + __half2float(stg[ra * SPITCH + c]) + cn[j];
                        tb2[j] = qb[c] + __half2float(stg[rb * SPITCH + c]) + cn[j];
                        sa += ta[j]; ssa += ta[j] * ta[j];
                        sb += tb2[j]; ssb += tb2[j] * tb2[j];
                    }
#pragma unroll
                    for (int o = 16; o; o >>= 1) {
                        sa  += __shfl_xor_sync(0xffffffffu, sa, o);
                        ssa += __shfl_xor_sync(0xffffffffu, ssa, o);
                        sb  += __shfl_xor_sync(0xffffffffu, sb, o);
                        ssb += __shfl_xor_sync(0xffffffffu, ssb, o);
                    }
                    float ma = sa * (1.f / DIM);
                    float rsa = rsqrtf(fmaxf(ssa * (1.f / DIM) - ma * ma, 0.f) + 1e-5f);
                    float mb = sb * (1.f / DIM);
                    float rsb = rsqrtf(fmaxf(ssb * (1.f / DIM) - mb * mb, 0.f) + 1e-5f);
                    float ga = gates_s[ra * 8 + n];
                    float gb2 = gates_s[rb * 8 + n];
#pragma unroll
                    for (int j = 0; j < 8; j++) {
                        acc[rp * 2 + 0][j] += ga  * ((ta[j]  - ma) * rsa * gm[j] + bt[j]);
                        acc[rp * 2 + 1][j] += gb2 * ((tb2[j] - mb) * rsb * gm[j] + bt[j]);
                    }
                }
            }

            if (n + 1 < NMOD) BAR_ARRIVE(BID_SFREE, 512);
        }

        // ---- final LN(q + acc), store (2-row interleaved) ----
        {
            float fg[8], fb[8];
#pragma unroll
            for (int j = 0; j < 8; j++) {
                int c = l + 32 * j;
                fg[j] = __ldg(final_ln_g + c); fb[j] = __ldg(final_ln_b + c);
            }
#pragma unroll
            for (int rp = 0; rp < 4; rp++) {
                int ra = cw * 8 + rp * 2, rb = ra + 1;
                const float* qa = x + (size_t)(r0 + ra) * XPITCH + mi * DIM;
                const float* qb = x + (size_t)(r0 + rb) * XPITCH + mi * DIM;
                float sa = 0.f, ssa = 0.f, sb = 0.f, ssb = 0.f;
#pragma unroll
                for (int j = 0; j < 8; j++) {
                    int c = l + 32 * j;
                    float t0 = qa[c] + acc[rp * 2 + 0][j];
                    float t1 = qb[c] + acc[rp * 2 + 1][j];
                    acc[rp * 2 + 0][j] = t0;
                    acc[rp * 2 + 1][j] = t1;
                    sa += t0; ssa += t0 * t0;
                    sb += t1; ssb += t1 * t1;
                }
#pragma unroll
                for (int o = 16; o; o >>= 1) {
                    sa  += __shfl_xor_sync(0xffffffffu, sa, o);
                    ssa += __shfl_xor_sync(0xffffffffu, ssa, o);
                    sb  += __shfl_xor_sync(0xffffffffu, sb, o);
                    ssb += __shfl_xor_sync(0xffffffffu, ssb, o);
                }
                float ma = sa * (1.f / DIM);
                float rsa = rsqrtf(fmaxf(ssa * (1.f / DIM) - ma * ma, 0.f) + 1e-5f);
                float mb = sb * (1.f / DIM);
                float rsb = rsqrtf(fmaxf(ssb * (1.f / DIM) - mb * mb, 0.f) + 1e-5f);
                float* oa = out + (size_t)(r0 + ra) * DIM;
                float* ob = out + (size_t)(r0 + rb) * DIM;
#pragma unroll
                for (int j = 0; j < 8; j++) {
                    int c = l + 32 * j;
                    oa[c] = (acc[rp * 2 + 0][j] - ma) * rsa * fg[j] + fb[j];
                    ob[c] = (acc[rp * 2 + 1][j] - mb) * rsb * fg[j] + fb[j];
                }
            }
        }
    }
}

// ------------------------------------------------------------------
extern "C" void kernel_launch(void* const* d_in, const int* in_sizes, int n_in,
                              void* d_out, int out_size) {
    (void)in_sizes; (void)n_in; (void)out_size;
    const float* x          = (const float*)d_in[0];
    const float* self_Wi    = (const float*)d_in[1];
    const float* self_bi    = (const float*)d_in[2];
    const float* self_Wo    = (const float*)d_in[3];
    const float* self_bo    = (const float*)d_in[4];
    const float* cross_Wi   = (const float*)d_in[5];
    const float* cross_bi   = (const float*)d_in[6];
    const float* cross_Wo   = (const float*)d_in[7];
    const float* cross_bo   = (const float*)d_in[8];
    const float* cross_ln_g = (const float*)d_in[9];
    const float* cross_ln_b = (const float*)d_in[10];
    const float* gate_ln_g  = (const float*)d_in[11];
    const float* gate_ln_b  = (const float*)d_in[12];
    const float* gate_W     = (const float*)d_in[13];
    const float* gate_b     = (const float*)d_in[14];
    const float* final_ln_g = (const float*)d_in[15];
    const float* final_ln_b = (const float*)d_in[16];
    const int*   modal_idx  = (const int*)d_in[17];
    float* out = (float*)d_out;

    static bool attr_set = false;
    if (!attr_set) {
        cudaFuncSetAttribute(fused_main_kernel,
                             cudaFuncAttributeMaxDynamicSharedMemorySize, SMEM_TOTAL);
        cudaFuncSetAttribute(fuse_weights_kernel,
                             cudaFuncAttributeMaxDynamicSharedMemorySize, PSM_TOTAL);
        attr_set = true;
    }

    fuse_weights_kernel<<<dim3(8, 4, 5), 256, PSM_TOTAL>>>(self_Wi, self_bi, self_Wo, self_bo,
                                                           cross_Wi, cross_bi, cross_Wo, cross_bo);
    fused_main_kernel<<<NROWS / TB, NTH, SMEM_TOTAL>>>(
        x, cross_ln_g, cross_ln_b, gate_ln_g, gate_ln_b,
        gate_W, gate_b, final_ln_g, final_ln_b, modal_idx, out);
}

// round 17
// speedup vs baseline: 1.3647x; 1.3647x over previous
#include <cuda_runtime.h>
#include <cuda_fp16.h>
#include <cstdint>

#define DIM 256
#define NMOD 5
#define NROWS 16384
#define TB 64
#define NTH 512
#define XPITCH (NMOD * DIM)

#define APITCH 264            // A_s pitch (fp16)
#define BPITCH 72             // B pitch (fp16), 64 K-cols + 8 pad
#define SPITCH 264            // stage pitch (fp16)
#define CHUNK_BYTES (256 * BPITCH * 2)   // 36864
#define CHUNK_U16   (CHUNK_BYTES / 16)   // 2304

// Fused per-branch matrices, PRE-PADDED fp16 image (chunk c = n*4+kc).
__device__ __align__(16) __half g_M[NMOD * 4][256][BPITCH];
__device__ float g_c[NMOD][DIM];

// ---------------- main-kernel smem layout ----------------
constexpr int SM_GA  = 0;                        // gates 64*8 f     = 2048
constexpr int SM_STG = 2048;                     // 64*264 fp16      = 33792
constexpr int SM_A   = SM_STG + 33792;           // 2 x 64*264 fp16  = 67584
constexpr int SM_B   = SM_A + 67584;             // 2 x 36864        = 73728
constexpr int SMEM_TOTAL = SM_B + 73728;         // 177152

// named barriers
#define BID_AREADY 1
#define BID_SFULL  2
#define BID_SFREE  3
#define BID_PROD   6
#define BAR_SYNC(id, cnt)   asm volatile("bar.sync %0, %1;"   :: "r"(id), "r"(cnt) : "memory")
#define BAR_ARRIVE(id, cnt) asm volatile("bar.arrive %0, %1;" :: "r"(id), "r"(cnt) : "memory")

// ---------------- helpers ----------------
__device__ __forceinline__ void ldsm_x4(uint32_t* r, const void* p) {
    uint32_t addr = (uint32_t)__cvta_generic_to_shared(p);
    asm volatile("ldmatrix.sync.aligned.m8n8.x4.shared.b16 {%0,%1,%2,%3}, [%4];"
                 : "=r"(r[0]), "=r"(r[1]), "=r"(r[2]), "=r"(r[3]) : "r"(addr));
}
__device__ __forceinline__ void mma16816f(float* d, const uint32_t* a, const uint32_t* b) {
    asm volatile("mma.sync.aligned.m16n8k16.row.col.f32.f16.f16.f32 "
                 "{%0,%1,%2,%3},{%4,%5,%6,%7},{%8,%9},{%0,%1,%2,%3};"
                 : "+f"(d[0]), "+f"(d[1]), "+f"(d[2]), "+f"(d[3])
                 : "r"(a[0]), "r"(a[1]), "r"(a[2]), "r"(a[3]), "r"(b[0]), "r"(b[1]));
}
__device__ __forceinline__ float warp_sum(float v) {
#pragma unroll
    for (int o = 16; o; o >>= 1) v += __shfl_xor_sync(0xffffffffu, v, o);
    return v;
}
__device__ __forceinline__ void cp_async16(void* smem, const void* g) {
    uint32_t s = (uint32_t)__cvta_generic_to_shared(smem);
    asm volatile("cp.async.cg.shared.global [%0], [%1], 16;\n" :: "r"(s), "l"(g));
}
__device__ __forceinline__ void cp_commit() { asm volatile("cp.async.commit_group;\n"); }
__device__ __forceinline__ uint32_t pkh2(float a, float b) {
    __half2 h = __floats2half2_rn(a, b);
    return *(uint32_t*)&h;
}

// ------------------------------------------------------------------
// prologue v2 (kept from R16, measured ~3.8us): grid (8, 4, 5) = 160 CTAs.
// CTA (bx, kc, n) computes the 32x64 tile M_n[bx*32..+32][kc*64..+64],
// K=256 resident, single sync phase. Bias by kc==0 CTAs.
// ------------------------------------------------------------------
constexpr int PSM_TOTAL = 16896 + 33792 + 1024;   // 51712

__global__ __launch_bounds__(256, 1)
void fuse_weights_kernel(const float* __restrict__ sWi, const float* __restrict__ sbi,
                         const float* __restrict__ sWo, const float* __restrict__ sbo,
                         const float* __restrict__ cWi, const float* __restrict__ cbi,
                         const float* __restrict__ cWo, const float* __restrict__ cbo) {
    extern __shared__ char sm[];
    __half* A_s = (__half*)sm;                       // [32][APITCH]
    __half* B_s = (__half*)(sm + 16896);             // [64][APITCH]  (k rows, j cols)
    float* bv_s = (float*)(sm + 16896 + 33792);      // [256]
    float* bred = (float*)B_s;                       // reuse after GEMM

    const int bx = blockIdx.x, kc = blockIdx.y, n = blockIdx.z;
    const float* Wo = (n == 0) ? sWo : cWo + (size_t)(n - 1) * DIM * DIM;
    const float* Wv = (n == 0) ? sWi + 2 * DIM * DIM
                               : cWi + (size_t)(n - 1) * 3 * DIM * DIM + 2 * DIM * DIM;
    const float* bv = (n == 0) ? sbi + 2 * DIM : cbi + (size_t)(n - 1) * 3 * DIM + 2 * DIM;
    const float* bo = (n == 0) ? sbo : cbo + (size_t)(n - 1) * DIM;

    const int tid = threadIdx.x;
    const int w = tid >> 5, l = tid & 31;
    const int wm = w & 1, wn = w >> 1;
    const int lq = l >> 2, lr = l & 3;

    bv_s[tid] = bv[tid];

    // A: Wo rows bx*32..+31, all 256 j  (fp16)
#pragma unroll
    for (int i = 0; i < 8; i++) {
        int e = tid + i * 256, r = e >> 6, c4 = (e & 63) << 2;
        float4 v = *(const float4*)(Wo + (size_t)(bx * 32 + r) * DIM + c4);
        __half* dst = A_s + r * APITCH + c4;
        *(uint32_t*)(dst)     = pkh2(v.x, v.y);
        *(uint32_t*)(dst + 2) = pkh2(v.z, v.w);
    }
    // B: B_s[k][j] = Wv[j][kc*64 + k], k 0..63, j 0..255 (coalesced along k)
#pragma unroll
    for (int i = 0; i < 16; i++) {
        int e = tid + i * 256;
        int k = e & 63, j4 = (e >> 6) << 2;
        float v0 = Wv[(size_t)(j4 + 0) * DIM + kc * 64 + k];
        float v1 = Wv[(size_t)(j4 + 1) * DIM + kc * 64 + k];
        float v2 = Wv[(size_t)(j4 + 2) * DIM + kc * 64 + k];
        float v3 = Wv[(size_t)(j4 + 3) * DIM + kc * 64 + k];
        __half* dst = B_s + k * APITCH + j4;
        *(uint32_t*)(dst)     = pkh2(v0, v1);
        *(uint32_t*)(dst + 2) = pkh2(v2, v3);
    }
    __syncthreads();

    // warp tile 16x16 (2M x 4N), K=256 in 16 ks steps, no barriers
    float cf[2][4];
#pragma unroll
    for (int nt = 0; nt < 2; nt++)
#pragma unroll
        for (int i = 0; i < 4; i++) cf[nt][i] = 0.f;

#pragma unroll
    for (int ks = 0; ks < 16; ks++) {
        uint32_t af[4];
        {
            int row = wm * 16 + (l & 7) + ((l >> 3) & 1) * 8;
            int col = ks * 16 + (l >> 4) * 8;
            ldsm_x4(af, A_s + row * APITCH + col);
        }
        uint32_t r4[4];
        {
            int row = wn * 16 + (l & 7) + (l >> 4) * 8;
            int col = ks * 16 + ((l >> 3) & 1) * 8;
            ldsm_x4(r4, B_s + row * APITCH + col);
        }
        mma16816f(cf[0], af, r4);
        mma16816f(cf[1], af, r4 + 2);
    }
    __syncthreads();   // B_s reads done (bred reuses it in kc==0)

    // store 32x64 tile to padded image chunk ch = n*4+kc
    {
        int ch = n * 4 + kc;
        int d = bx * 32 + wm * 16 + lq;
#pragma unroll
        for (int nt = 0; nt < 2; nt++) {
            int kk = wn * 16 + nt * 8 + 2 * lr;
            *(uint32_t*)&g_M[ch][d][kk]     = pkh2(cf[nt][0], cf[nt][1]);
            *(uint32_t*)&g_M[ch][d + 8][kk] = pkh2(cf[nt][2], cf[nt][3]);
        }
    }

    // bias (kc==0 CTAs only): c[d] = Wo[d,:] @ bv + bo[d]
    if (kc == 0) {
        int row = tid & 31, part = tid >> 5;
        float s = 0.f;
#pragma unroll 8
        for (int j = 0; j < 32; j++) {
            int jj = part * 32 + j;
            s += __half2float(A_s[row * APITCH + jj]) * bv_s[jj];
        }
        bred[part * 32 + row] = s;
        __syncthreads();
        if (tid < 32) {
            float c = bo[bx * 32 + tid];
#pragma unroll
            for (int p = 0; p < 8; p++) c += bred[p * 32 + tid];
            g_c[n][bx * 32 + tid] = c;
        }
    }
}

// ------------------------------------------------------------------
// main kernel: EXACT R15 (measured 84.35us): warp-specialized
// producer/consumer, sequential gates, 2-row interleaved cross/final LN.
// ------------------------------------------------------------------
__global__ __launch_bounds__(NTH, 1)
void fused_main_kernel(const float* __restrict__ x,
                       const float* __restrict__ cross_ln_g, const float* __restrict__ cross_ln_b,
                       const float* __restrict__ gate_ln_g, const float* __restrict__ gate_ln_b,
                       const float* __restrict__ gate_W, const float* __restrict__ gate_b,
                       const float* __restrict__ final_ln_g, const float* __restrict__ final_ln_b,
                       const int* __restrict__ modal_idx, float* __restrict__ out) {
    extern __shared__ char sm[];
    float* gates_s = (float*)(sm + SM_GA);      // [64][8]
    __half* stg    = (__half*)(sm + SM_STG);    // [64][SPITCH] fp16
    __half* A_s    = (__half*)(sm + SM_A);      // [2][64][APITCH]
    char* B_s      = sm + SM_B;                 // [2][CHUNK_BYTES]

    const int tid = threadIdx.x;
    const int w = tid >> 5, l = tid & 31;
    const int mi = *modal_idx;
    const int r0 = blockIdx.x * TB;

    // producers issue B prefetch (chunks 0,1)
    if (tid < 256) {
        const char* src = (const char*)g_M;
#pragma unroll
        for (int i = 0; i < 9; i++) {
            int e = tid + i * 256;
            if (e < CHUNK_U16) cp_async16(B_s + e * 16, src + e * 16);
        }
        cp_commit();
#pragma unroll
        for (int i = 0; i < 9; i++) {
            int e = tid + i * 256;
            if (e < CHUNK_U16) cp_async16(B_s + CHUNK_BYTES + e * 16, src + CHUNK_BYTES + e * 16);
        }
        cp_commit();
    }

    // A0 fill by all 512 threads (branch 0 = modality mi)
#pragma unroll
    for (int i = 0; i < 8; i++) {
        int e = tid + i * NTH, r = e >> 6, c4 = (e & 63) << 2;
        float4 v = *(const float4*)(x + (size_t)(r0 + r) * XPITCH + mi * DIM + c4);
        __half* dst = A_s + r * APITCH + c4;
        *(uint32_t*)(dst)     = pkh2(v.x, v.y);
        *(uint32_t*)(dst + 2) = pkh2(v.z, v.w);
    }
    __syncthreads();

    if (w < 8) {
        // ===================== PRODUCER (8 warps) =====================
        const int wm = w & 1, wn = w >> 1;
        const int lq = l >> 2, lr = l & 3;

#pragma unroll 1
        for (int n = 0; n < NMOD; n++) {
            if (n) BAR_SYNC(BID_AREADY, 512);     // A[n&1] filled by consumers
            const __half* As = A_s + (n & 1) * (TB * APITCH);

            float cf[2][8][4];
#pragma unroll
            for (int mt = 0; mt < 2; mt++)
#pragma unroll
                for (int nt = 0; nt < 8; nt++)
#pragma unroll
                    for (int i = 0; i < 4; i++) cf[mt][nt][i] = 0.f;

#pragma unroll 1
            for (int kc = 0; kc < 4; kc++) {
                int c = n * 4 + kc;
                asm volatile("cp.async.wait_group 0;\n");
                BAR_SYNC(BID_PROD, 256);          // chunk c visible; old buf free
                if (c + 1 < 20) {
                    const char* src = (const char*)g_M + (size_t)(c + 1) * CHUNK_BYTES;
                    char* dst = B_s + ((c + 1) & 1) * CHUNK_BYTES;
#pragma unroll
                    for (int i = 0; i < 9; i++) {
                        int e = tid + i * 256;
                        if (e < CHUNK_U16) cp_async16(dst + e * 16, src + e * 16);
                    }
                    cp_commit();
                }
                const __half* Bc = (const __half*)(B_s + (c & 1) * CHUNK_BYTES);
#pragma unroll
                for (int ks = 0; ks < 4; ks++) {
                    uint32_t af[2][4];
#pragma unroll
                    for (int mt = 0; mt < 2; mt++) {
                        int row = wm * 32 + mt * 16 + (l & 7) + ((l >> 3) & 1) * 8;
                        int col = kc * 64 + ks * 16 + (l >> 4) * 8;
                        ldsm_x4(af[mt], As + row * APITCH + col);
                    }
                    uint32_t bfr[8][2];
#pragma unroll
                    for (int np = 0; np < 4; np++) {
                        int row = wn * 64 + np * 16 + (l & 7) + (l >> 4) * 8;
                        int col = ks * 16 + ((l >> 3) & 1) * 8;
                        uint32_t r4[4];
                        ldsm_x4(r4, Bc + row * BPITCH + col);
                        bfr[2 * np][0] = r4[0]; bfr[2 * np][1] = r4[1];
                        bfr[2 * np + 1][0] = r4[2]; bfr[2 * np + 1][1] = r4[3];
                    }
#pragma unroll
                    for (int mt = 0; mt < 2; mt++)
#pragma unroll
                        for (int nt = 0; nt < 8; nt++)
                            mma16816f(cf[mt][nt], af[mt], bfr[nt]);
                }
            }

            // publish a-tile to stage (fp16)
            if (n) BAR_SYNC(BID_SFREE, 512);      // consumers drained stage n-1
#pragma unroll
            for (int mt = 0; mt < 2; mt++)
#pragma unroll
                for (int nt = 0; nt < 8; nt++) {
                    int row = wm * 32 + mt * 16 + lq;
                    int col = wn * 64 + nt * 8 + 2 * lr;
                    *(uint32_t*)(stg + row * SPITCH + col)       = pkh2(cf[mt][nt][0], cf[mt][nt][1]);
                    *(uint32_t*)(stg + (row + 8) * SPITCH + col) = pkh2(cf[mt][nt][2], cf[mt][nt][3]);
                }
            __threadfence_block();
            BAR_ARRIVE(BID_SFULL, 512);
        }
    } else {
        // ===================== CONSUMER (8 warps) =====================
        const int cw = w - 8;            // 0..7, owns rows cw*8 .. cw*8+7
        const int ctid = tid - 256;      // 0..255

        // gates for my 8 rows (consts via __ldg; overlaps producer GEMM 0)
        {
            float gb[5];
#pragma unroll
            for (int n = 0; n < 5; n++) gb[n] = __ldg(gate_b + n);
#pragma unroll 1
            for (int ri = 0; ri < 8; ri++) {
                int r = cw * 8 + ri;
                const float* xr = x + (size_t)(r0 + r) * XPITCH + mi * DIM;
                float qv[8], sum = 0.f, sq = 0.f;
#pragma unroll
                for (int j = 0; j < 8; j++) {
                    qv[j] = xr[l + 32 * j];
                    sum += qv[j]; sq += qv[j] * qv[j];
                }
                sum = warp_sum(sum); sq = warp_sum(sq);
                float m = sum * (1.f / DIM);
                float rs = rsqrtf(fmaxf(sq * (1.f / DIM) - m * m, 0.f) + 1e-5f);
                float lnv[8];
#pragma unroll
                for (int j = 0; j < 8; j++) {
                    int c = l + 32 * j;
                    lnv[j] = (qv[j] - m) * rs * __ldg(gate_ln_g + c) + __ldg(gate_ln_b + c);
                }
                float lg[5];
#pragma unroll
                for (int n = 0; n < 5; n++) {
                    float s = 0.f;
#pragma unroll
                    for (int j = 0; j < 8; j++) s += lnv[j] * __ldg(gate_W + n * DIM + l + 32 * j);
                    lg[n] = warp_sum(s) + gb[n];
                }
                float mx = lg[0];
#pragma unroll
                for (int n = 1; n < 5; n++) mx = fmaxf(mx, lg[n]);
                float es = 0.f;
#pragma unroll
                for (int n = 0; n < 5; n++) { lg[n] = expf(lg[n] - mx); es += lg[n]; }
                if (l == 0) {
                    float inv = 1.f / es;
#pragma unroll
                    for (int n = 0; n < 5; n++) gates_s[r * 8 + n] = lg[n] * inv;
                }
            }
            __syncwarp();
        }

        float acc[8][8];

#pragma unroll 1
        for (int n = 0; n < NMOD; n++) {
            // fill A for branch n+1 (buffer (n+1)&1 free: GEMM n-1 done)
            if (n + 1 < NMOD) {
                int m2 = n + 1;
                int mod = ((m2 - 1) < mi) ? (m2 - 1) : m2;
                __half* Ad = A_s + (m2 & 1) * (TB * APITCH);
#pragma unroll
                for (int i = 0; i < 16; i++) {
                    int e = ctid + i * 256, r = e >> 6, c4 = (e & 63) << 2;
                    float4 v = *(const float4*)(x + (size_t)(r0 + r) * XPITCH + mod * DIM + c4);
                    __half* dst = Ad + r * APITCH + c4;
                    *(uint32_t*)(dst)     = pkh2(v.x, v.y);
                    *(uint32_t*)(dst + 2) = pkh2(v.z, v.w);
                }
                __threadfence_block();
                BAR_ARRIVE(BID_AREADY, 512);
            }

            BAR_SYNC(BID_SFULL, 512);   // stage n ready

            if (n == 0) {
                float c0[8];
#pragma unroll
                for (int j = 0; j < 8; j++) c0[j] = g_c[0][l + 32 * j];
#pragma unroll
                for (int ri = 0; ri < 8; ri++) {
                    int row = cw * 8 + ri;
                    float g0 = gates_s[row * 8 + 0];
#pragma unroll
                    for (int j = 0; j < 8; j++)
                        acc[ri][j] = g0 * (__half2float(stg[row * SPITCH + l + 32 * j]) + c0[j]);
                }
            } else {
                float cn[8], gm[8], bt[8];
                const float* gam = cross_ln_g + (n - 1) * DIM;
                const float* bet = cross_ln_b + (n - 1) * DIM;
#pragma unroll
                for (int j = 0; j < 8; j++) {
                    int c = l + 32 * j;
                    cn[j] = g_c[n][c]; gm[j] = __ldg(gam + c); bt[j] = __ldg(bet + c);
                }
                // 2-row interleaved LN (4 reduction chains in flight)
#pragma unroll
                for (int rp = 0; rp < 4; rp++) {
                    int ra = cw * 8 + rp * 2, rb = ra + 1;
                    const float* qa = x + (size_t)(r0 + ra) * XPITCH + mi * DIM;
                    const float* qb = x + (size_t)(r0 + rb) * XPITCH + mi * DIM;
                    float ta[8], tb2[8];
                    float sa = 0.f, ssa = 0.f, sb = 0.f, ssb = 0.f;
#pragma unroll
                    for (int j = 0; j < 8; j++) {
                        int c = l + 32 * j;
                        ta[j]  = qa[c] + __half2float(stg[ra * SPITCH + c]) + cn[j];
                        tb2[j] = qb[c] + __half2float(stg[rb * SPITCH + c]) + cn[j];
                        sa += ta[j]; ssa += ta[j] * ta[j];
                        sb += tb2[j]; ssb += tb2[j] * tb2[j];
                    }
#pragma unroll
                    for (int o = 16; o; o >>= 1) {
                        sa  += __shfl_xor_sync(0xffffffffu, sa, o);
                        ssa += __shfl_xor_sync(0xffffffffu, ssa, o);
                        sb  += __shfl_xor_sync(0xffffffffu, sb, o);
                        ssb += __shfl_xor_sync(0xffffffffu, ssb, o);
                    }
                    float ma = sa * (1.f / DIM);
                    float rsa = rsqrtf(fmaxf(ssa * (1.f / DIM) - ma * ma, 0.f) + 1e-5f);
                    float mb = sb * (1.f / DIM);
                    float rsb = rsqrtf(fmaxf(ssb * (1.f / DIM) - mb * mb, 0.f) + 1e-5f);
                    float ga = gates_s[ra * 8 + n];
                    float gb2 = gates_s[rb * 8 + n];
#pragma unroll
                    for (int j = 0; j < 8; j++) {
                        acc[rp * 2 + 0][j] += ga  * ((ta[j]  - ma) * rsa * gm[j] + bt[j]);
                        acc[rp * 2 + 1][j] += gb2 * ((tb2[j] - mb) * rsb * gm[j] + bt[j]);
                    }
                }
            }

            if (n + 1 < NMOD) BAR_ARRIVE(BID_SFREE, 512);
        }

        // ---- final LN(q + acc), store (2-row interleaved) ----
        {
            float fg[8], fb[8];
#pragma unroll
            for (int j = 0; j < 8; j++) {
                int c = l + 32 * j;
                fg[j] = __ldg(final_ln_g + c); fb[j] = __ldg(final_ln_b + c);
            }
#pragma unroll
            for (int rp = 0; rp < 4; rp++) {
                int ra = cw * 8 + rp * 2, rb = ra + 1;
                const float* qa = x + (size_t)(r0 + ra) * XPITCH + mi * DIM;
                const float* qb = x + (size_t)(r0 + rb) * XPITCH + mi * DIM;
                float sa = 0.f, ssa = 0.f, sb = 0.f, ssb = 0.f;
#pragma unroll
                for (int j = 0; j < 8; j++) {
                    int c = l + 32 * j;
                    float t0 = qa[c] + acc[rp * 2 + 0][j];
                    float t1 = qb[c] + acc[rp * 2 + 1][j];
                    acc[rp * 2 + 0][j] = t0;
                    acc[rp * 2 + 1][j] = t1;
                    sa += t0; ssa += t0 * t0;
                    sb += t1; ssb += t1 * t1;
                }
#pragma unroll
                for (int o = 16; o; o >>= 1) {
                    sa  += __shfl_xor_sync(0xffffffffu, sa, o);
                    ssa += __shfl_xor_sync(0xffffffffu, ssa, o);
                    sb  += __shfl_xor_sync(0xffffffffu, sb, o);
                    ssb += __shfl_xor_sync(0xffffffffu, ssb, o);
                }
                float ma = sa * (1.f / DIM);
                float rsa = rsqrtf(fmaxf(ssa * (1.f / DIM) - ma * ma, 0.f) + 1e-5f);
                float mb = sb * (1.f / DIM);
                float rsb = rsqrtf(fmaxf(ssb * (1.f / DIM) - mb * mb, 0.f) + 1e-5f);
                float* oa = out + (size_t)(r0 + ra) * DIM;
                float* ob = out + (size_t)(r0 + rb) * DIM;
#pragma unroll
                for (int j = 0; j < 8; j++) {
                    int c = l + 32 * j;
                    oa[c] = (acc[rp * 2 + 0][j] - ma) * rsa * fg[j] + fb[j];
                    ob[c] = (acc[rp * 2 + 1][j] - mb) * rsb * fg[j] + fb[j];
                }
            }
        }
    }
}

// ------------------------------------------------------------------
extern "C" void kernel_launch(void* const* d_in, const int* in_sizes, int n_in,
                              void* d_out, int out_size) {
    (void)in_sizes; (void)n_in; (void)out_size;
    const float* x          = (const float*)d_in[0];
    const float* self_Wi    = (const float*)d_in[1];
    const float* self_bi    = (const float*)d_in[2];
    const float* self_Wo    = (const float*)d_in[3];
    const float* self_bo    = (const float*)d_in[4];
    const float* cross_Wi   = (const float*)d_in[5];
    const float* cross_bi   = (const float*)d_in[6];
    const float* cross_Wo   = (const float*)d_in[7];
    const float* cross_bo   = (const float*)d_in[8];
    const float* cross_ln_g = (const float*)d_in[9];
    const float* cross_ln_b = (const float*)d_in[10];
    const float* gate_ln_g  = (const float*)d_in[11];
    const float* gate_ln_b  = (const float*)d_in[12];
    const float* gate_W     = (const float*)d_in[13];
    const float* gate_b     = (const float*)d_in[14];
    const float* final_ln_g = (const float*)d_in[15];
    const float* final_ln_b = (const float*)d_in[16];
    const int*   modal_idx  = (const int*)d_in[17];
    float* out = (float*)d_out;

    static bool attr_set = false;
    if (!attr_set) {
        cudaFuncSetAttribute(fused_main_kernel,
                             cudaFuncAttributeMaxDynamicSharedMemorySize, SMEM_TOTAL);
        cudaFuncSetAttribute(fuse_weights_kernel,
                             cudaFuncAttributeMaxDynamicSharedMemorySize, PSM_TOTAL);
        attr_set = true;
    }

    fuse_weights_kernel<<<dim3(8, 4, 5), 256, PSM_TOTAL>>>(self_Wi, self_bi, self_Wo, self_bo,
                                                           cross_Wi, cross_bi, cross_Wo, cross_bo);
    fused_main_kernel<<<NROWS / TB, NTH, SMEM_TOTAL>>>(
        x, cross_ln_g, cross_ln_b, gate_ln_g, gate_ln_b,
        gate_W, gate_b, final_ln_g, final_ln_b, modal_idx, out);
}